// round 11
// baseline (speedup 1.0000x reference)
#include <cuda_runtime.h>
#include <cuda_bf16.h>

// Problem constants (fixed by the reference)
#define BB 2
#define CC 64
#define HH 512
#define WW 512
#define HW (HH * WW)          // 262144
#define NN 4096
#define KK 5
#define NPAIR (BB * NN)       // 8192
#define INV_MAXDIST (1.0f / 724.07733f)
#define FEAT_THRESH_NOMATCH 16.0f
// fixed-point: fp_i = total_i * FP_SCALE, FP_SCALE = (1/24576) * 2^48 = 2^35/3
// finalize: out = (sum fp_i) * 2^-48
#define FP_SCALE (34359738368.0f / 3.0f)          // 1.1453246123e10
#define FP_INV   (1.0 / 281474976710656.0)        // 2^-48

// Persistent grid: 576 blocks of 256 threads. __launch_bounds__(256,4) forces
// <=64 regs -> >=4 blocks/SM; smem 20.6KB*4=82KB<=228KB; 576 <= 4*148 = 592,
// so ALL blocks are resident simultaneously -> software grid barriers are safe.
#define NBLK 576
#define NWARP (NBLK * 8)

// Scratch (allocation-free rule: __device__ globals; zero-initialized at load)
__device__ float g_fr[NPAIR * CC];      // compacted ref features   [b][i][c]
__device__ float g_fo[NPAIR * CC];      // compacted other features [b][i][c]
__device__ int   g_order[4][NN];        // per set: packed (lin<<12 | point id)
__device__ unsigned long long g_isum;   // fixed-point loss accumulator
__device__ unsigned int g_ticket;       // completion counter (blocks)
__device__ volatile unsigned int g_barA;  // grid barrier counters
__device__ volatile unsigned int g_barB;

__device__ __forceinline__ void grid_barrier(volatile unsigned int* ctr) {
    __syncthreads();
    if (threadIdx.x == 0) {
        __threadfence();                       // release prior writes
        atomicAdd((unsigned int*)ctr, 1u);
        while (*ctr < NBLK) { }                // volatile spin
        __threadfence();                       // acquire
    }
    __syncthreads();
}

__global__ void __launch_bounds__(256, 4) fused_kernel(
        const float* __restrict__ ref,
        const float* __restrict__ oth,
        const float* __restrict__ weights,
        const int* __restrict__ inds_ref,
        const int* __restrict__ inds_other,
        const int* __restrict__ rand_inds,
        float* __restrict__ out) {
    __shared__ int lin_s[NN];     // 16 KB (sort phase, blocks 0..3 only)
    __shared__ int hist[512];
    __shared__ int wsum[8];
    __shared__ int offs[512];
    __shared__ long long s_fp[8];

    int tid  = threadIdx.x;
    int lane = tid & 31;
    int wib  = tid >> 5;          // warp in block (0..7)
    int blk  = blockIdx.x;

    // ================= Phase S: counting sort (blocks 0..3) =================
    if (blk < 4) {
        int s = blk;              // 0,1 = ref b0,b1 ; 2,3 = oth b0,b1
        int t = s >> 1, b = s & 1;
        const int* inds = t ? inds_other : inds_ref;

        hist[tid] = 0;
        hist[tid + 256] = 0;
        __syncthreads();

        for (int i = tid; i < NN; i += 256) {
            int x = inds[b * 2 * NN + i];
            int y = inds[b * 2 * NN + NN + i];
            int lin = (y << 9) | x;       // 512*y + x
            lin_s[i] = lin;
            atomicAdd(&hist[y], 1);
        }
        __syncthreads();

        // scan 512 buckets with 256 threads: thread t owns buckets 2t, 2t+1
        int h0 = hist[2 * tid];
        int h1 = hist[2 * tid + 1];
        int psum = h0 + h1;
        int v = psum;                      // inclusive scan of pair-sums
#pragma unroll
        for (int d = 1; d < 32; d <<= 1) {
            int u = __shfl_up_sync(0xFFFFFFFFu, v, d);
            if (lane >= d) v += u;
        }
        if (lane == 31) wsum[wib] = v;     // 8 warp totals
        __syncthreads();
        if (tid < 32) {
            int u = (tid < 8) ? wsum[tid] : 0;
#pragma unroll
            for (int d = 1; d < 8; d <<= 1) {
                int x2 = __shfl_up_sync(0xFFFFFFFFu, u, d);
                if (lane >= d) u += x2;
            }
            if (tid < 8) wsum[tid] = u;    // inclusive across warps
        }
        __syncthreads();
        int base = ((wib > 0) ? wsum[wib - 1] : 0) + (v - psum);  // excl pairs
        offs[2 * tid]     = base;
        offs[2 * tid + 1] = base + h0;
        __syncthreads();

        for (int i = tid; i < NN; i += 256) {
            int lin = lin_s[i];
            int pos = atomicAdd(&offs[lin >> 9], 1);
            g_order[s][pos] = (lin << 12) | i;
        }
    }
    grid_barrier(&g_barA);

    // ================= Phase G: sorted gather =================
    // slot <-> (set, channel-group of 4, chunk of 32 sorted points)
    for (int slot = blk * 8 + wib; slot < 8192; slot += NWARP) {
        int s    = slot >> 11;
        int qg   = (slot >> 7) & 15;
        int chnk = slot & 127;
        int t = s >> 1, b = s & 1;

        int packed = g_order[s][chnk * 32 + lane];
        int lin = packed >> 12;
        int id  = packed & 4095;

        const float* src = (t ? oth : ref) + (size_t)(b * CC + 4 * qg) * HW + lin;
        float v0 = __ldg(src + 0 * HW);
        float v1 = __ldg(src + 1 * HW);
        float v2 = __ldg(src + 2 * HW);
        float v3 = __ldg(src + 3 * HW);

        float* dst = (t ? g_fo : g_fr) + (size_t)((b << 12) | id) * CC + 4 * qg;
        *reinterpret_cast<float4*>(dst) = make_float4(v0, v1, v2, v3);
    }
    grid_barrier(&g_barB);

    // ================= Phase M: match + deterministic reduce =================
    long long fp_acc = 0;
    for (int pair = blk * 8 + wib; pair < NPAIR; pair += NWARP) {
        int b = pair >> 12;
        int i = pair & (NN - 1);

        const float2* frp = reinterpret_cast<const float2*>(g_fr + (size_t)pair * CC);
        const float2* fop = reinterpret_cast<const float2*>(g_fo + (size_t)pair * CC);
        float2 fr = frp[lane];
        float2 fo = fop[lane];
        float d0 = fr.x - fo.x, d1 = fr.y - fo.y;
        float sm = d0 * d0 + d1 * d1;

        int   jarr[KK];
        float sk[KK];
        const int* ri = rand_inds + (size_t)pair * KK;
#pragma unroll
        for (int k = 0; k < KK; k++) {
            int j = __ldg(ri + k);             // uniform across warp
            jarr[k] = j;
            const float2* fo_j =
                reinterpret_cast<const float2*>(g_fo + (size_t)(b * NN + j) * CC);
            float2 fj = fo_j[lane];
            float e0 = fr.x - fj.x, e1 = fr.y - fj.y;
            sk[k] = e0 * e0 + e1 * e1;
        }

#pragma unroll
        for (int off = 16; off > 0; off >>= 1) {
            sm += __shfl_down_sync(0xFFFFFFFFu, sm, off);
#pragma unroll
            for (int k = 0; k < KK; k++)
                sk[k] += __shfl_down_sync(0xFFFFFFFFu, sk[k], off);
        }

        if (lane == 0) {
            int xr = inds_ref[b * 2 * NN + i];
            int yr = inds_ref[b * 2 * NN + NN + i];
            float total = weights[b * NN + i] * fmaxf(sm, 0.0f);
#pragma unroll
            for (int k = 0; k < KK; k++) {
                int j  = jarr[k];
                float xj = (float)inds_ref[b * 2 * NN + j];
                float yj = (float)inds_ref[b * 2 * NN + NN + j];
                float dx = (float)xr - xj;
                float dy = (float)yr - yj;
                float dist = sqrtf(dx * dx + dy * dy);
                total += (-dist * INV_MAXDIST) * fminf(sk[k], FEAT_THRESH_NOMATCH);
            }
            fp_acc += llrintf(total * FP_SCALE);
        }
    }

    if (lane == 0) s_fp[wib] = fp_acc;
    __syncthreads();
    if (tid == 0) {
        long long bsum = 0;
#pragma unroll
        for (int k = 0; k < 8; k++) bsum += s_fp[k];
        atomicAdd(&g_isum, (unsigned long long)bsum);
        __threadfence();
        unsigned int t = atomicAdd(&g_ticket, 1u);
        if (t == NBLK - 1) {
            // every block has passed both barriers and contributed
            long long s = (long long)g_isum;
            out[0] = (float)((double)s * FP_INV);
            // reset ALL persistent state for the next graph replay
            g_isum = 0ULL;
            g_ticket = 0u;
            g_barA = 0u;
            g_barB = 0u;
        }
    }
}

extern "C" void kernel_launch(void* const* d_in, const int* in_sizes, int n_in,
                              void* d_out, int out_size) {
    const float* inputs_ref   = (const float*)d_in[0];
    const float* inputs_other = (const float*)d_in[1];
    const float* weights      = (const float*)d_in[2];
    const int*   inds_ref     = (const int*)d_in[3];
    const int*   inds_other   = (const int*)d_in[4];
    const int*   rand_inds    = (const int*)d_in[5];
    float* out = (float*)d_out;

    fused_kernel<<<NBLK, 256>>>(inputs_ref, inputs_other, weights,
                                inds_ref, inds_other, rand_inds, out);
}